// round 1
// baseline (speedup 1.0000x reference)
#include <cuda_runtime.h>
#include <math.h>

#define HH 64
#define WW 64
#define BB 2
#define CC 128
#define NH 4
#define DH 32
#define KS 7
#define KK 49
#define NTOK (BB*HH*WW)   // 8192
#define QKV_STRIDE (3*CC) // 384

// scratch (device globals: no allocation allowed)
__device__ float g_qkv[NTOK * 3 * CC];   // 12.6 MB
__device__ float g_att[NTOK * CC];       //  4.2 MB
__device__ float g_y1 [NTOK * CC];       //  4.2 MB
__device__ float g_y2 [NTOK * CC];       //  4.2 MB

// ----------------------------------------------------------------------------
// SGEMM: C[M=8192, N] = A(tokens x 128) @ W^T + bias
// a_nchw: A[t][c] = X[b][c][spatial]  (layer-0 input is NCHW)
// tile 64x64, BK=64, 256 threads, 4x4 microtile
// ----------------------------------------------------------------------------
__global__ void sgemm_kernel(const float* __restrict__ A, int a_nchw,
                             const float* __restrict__ W,
                             const float* __restrict__ bias,
                             float* __restrict__ Cout, int N)
{
    __shared__ float sA[64][65];   // [k][m], padded
    __shared__ float sB[64][65];   // [k][n], padded

    const int bm = blockIdx.x * 64;
    const int bn = blockIdx.y * 64;
    const int tid = threadIdx.x;
    const int tx = tid & 15;       // n-tile
    const int ty = tid >> 4;       // m-tile

    float acc[4][4] = {};

    for (int k0 = 0; k0 < CC; k0 += 64) {
        // --- load A tile ---
        if (a_nchw) {
            // m fastest -> consecutive spatial -> coalesced in NCHW
            for (int idx = tid; idx < 64*64; idx += 256) {
                int m = idx & 63, k = idx >> 6;
                int t = bm + m;
                int b = t >> 12, sp = t & 4095;
                sA[k][m] = A[(b*CC + (k0 + k))*4096 + sp];
            }
        } else {
            // k fastest -> coalesced in token-major [t][c]
            for (int idx = tid; idx < 64*64; idx += 256) {
                int k = idx & 63, m = idx >> 6;
                sA[k][m] = A[(bm + m)*CC + k0 + k];
            }
        }
        // --- load W tile (row-major [n][k], k contiguous) ---
        for (int idx = tid; idx < 64*64; idx += 256) {
            int k = idx & 63, n = idx >> 6;
            sB[k][n] = W[(bn + n)*CC + k0 + k];
        }
        __syncthreads();

        #pragma unroll
        for (int k = 0; k < 64; k++) {
            float a[4], b[4];
            #pragma unroll
            for (int i = 0; i < 4; i++) a[i] = sA[k][ty*4 + i];
            #pragma unroll
            for (int j = 0; j < 4; j++) b[j] = sB[k][tx*4 + j];
            #pragma unroll
            for (int i = 0; i < 4; i++)
                #pragma unroll
                for (int j = 0; j < 4; j++)
                    acc[i][j] += a[i] * b[j];
        }
        __syncthreads();
    }

    #pragma unroll
    for (int i = 0; i < 4; i++) {
        int t = bm + ty*4 + i;
        #pragma unroll
        for (int j = 0; j < 4; j++) {
            int n = bn + tx*4 + j;
            Cout[t*N + n] = acc[i][j] + bias[n];
        }
    }
}

// ----------------------------------------------------------------------------
// Neighborhood attention: one block per pixel, 128 threads, warp = head,
// lane = head-dim channel.
// ----------------------------------------------------------------------------
__global__ void attn_kernel(const float* __restrict__ qkv,
                            const float* __restrict__ rpb,   // [NH][13][13]
                            float* __restrict__ out)
{
    __shared__ float kwin[KK][133];   // pitch 133: stride-5 banks, conflict-free
    __shared__ float qs[NH][32];
    __shared__ float sc[NH][KK];

    const int t = blockIdx.x;
    const int b = t >> 12;
    const int sp = t & 4095;
    const int i = sp >> 6, j = sp & 63;
    const int si = min(max(i - 3, 0), HH - KS);
    const int sj = min(max(j - 3, 0), WW - KS);
    const int tid = threadIdx.x;

    // q into smem (scaled)
    {
        int h = tid >> 5, d = tid & 31;
        qs[h][d] = qkv[t*QKV_STRIDE + h*DH + d] * 0.17677669529663687f; // 1/sqrt(32)
    }
    // k window into smem: 49 x 128, coalesced per neighbor
    for (int n = 0; n < KK; n++) {
        int ii = si + n/7, jj = sj + n%7;
        int tt = (b*HH + ii)*WW + jj;
        kwin[n][tid] = qkv[tt*QKV_STRIDE + CC + tid];
    }
    __syncthreads();

    const int h = tid >> 5;
    const int lane = tid & 31;
    const float* rp = rpb + h*13*13;

    // scores: lane handles neighbor 'lane' (and lane+32 if valid)
    #pragma unroll
    for (int rep = 0; rep < 2; rep++) {
        int n = lane + rep*32;
        if (n < KK) {
            float s = 0.f;
            #pragma unroll
            for (int d = 0; d < DH; d++)
                s += qs[h][d] * kwin[n][h*DH + d];
            int p = n/7, q = n%7;
            int bi = p + (KS-1) - (i - si);
            int bj = q + (KS-1) - (j - sj);
            s += rp[bi*13 + bj];
            sc[h][n] = s;
        }
    }
    __syncwarp();

    // softmax over 49 (per warp)
    float m = -1e30f;
    for (int n = lane; n < KK; n += 32) m = fmaxf(m, sc[h][n]);
    #pragma unroll
    for (int o = 16; o > 0; o >>= 1) m = fmaxf(m, __shfl_xor_sync(0xffffffffu, m, o));

    float sum = 0.f;
    for (int n = lane; n < KK; n += 32) {
        float e = __expf(sc[h][n] - m);
        sc[h][n] = e;
        sum += e;
    }
    #pragma unroll
    for (int o = 16; o > 0; o >>= 1) sum += __shfl_xor_sync(0xffffffffu, sum, o);
    const float inv = 1.f / sum;
    __syncwarp();

    // AV: V read directly from global (L1-cached, coalesced 32-float per warp)
    float o = 0.f;
    #pragma unroll 7
    for (int n = 0; n < KK; n++) {
        int ii = si + n/7, jj = sj + n%7;
        int tt = (b*HH + ii)*WW + jj;
        o += sc[h][n] * qkv[tt*QKV_STRIDE + 2*CC + h*DH + lane];
    }
    out[t*CC + h*DH + lane] = o * inv;
}

// ----------------------------------------------------------------------------
// Final LayerNorm over C + NHWC -> NCHW transpose.
// Block per (b, i) image row: 64 tokens x 128 channels.
// ----------------------------------------------------------------------------
__global__ void ln_kernel(const float* __restrict__ y,
                          const float* __restrict__ g,
                          const float* __restrict__ bta,
                          float* __restrict__ out)
{
    __shared__ float s[64][133];
    __shared__ float mu[64], rs[64];

    const int row = blockIdx.x;        // 0..127
    const int b = row >> 6, i = row & 63;
    const int base = row * 64 * CC;
    const int tid = threadIdx.x;       // 256

    for (int idx = tid; idx < 64*CC; idx += 256) {
        int jj = idx >> 7, c = idx & 127;
        s[jj][c] = y[base + idx];
    }
    __syncthreads();

    if (tid < 64) {
        float sum = 0.f, sq = 0.f;
        #pragma unroll 8
        for (int c = 0; c < CC; c++) {
            float v = s[tid][c];
            sum += v; sq += v*v;
        }
        float m = sum * (1.f/CC);
        mu[tid] = m;
        rs[tid] = rsqrtf(sq * (1.f/CC) - m*m + 1e-5f);
    }
    __syncthreads();

    for (int idx = tid; idx < 64*CC; idx += 256) {
        int c = idx >> 6, jj = idx & 63;            // jj fastest -> coalesced out
        float v = (s[jj][c] - mu[jj]) * rs[jj] * g[c] + bta[c];
        out[((b*CC + c)*HH + i)*WW + jj] = v;
    }
}

// ----------------------------------------------------------------------------
extern "C" void kernel_launch(void* const* d_in, const int* in_sizes, int n_in,
                              void* d_out, int out_size)
{
    const float* x      = (const float*)d_in[0];   // (2,128,64,64)
    const float* qkv_w  = (const float*)d_in[1];   // (2,384,128)
    const float* qkv_b  = (const float*)d_in[2];   // (2,384)
    const float* rpb    = (const float*)d_in[3];   // (2,4,13,13)
    const float* proj_w = (const float*)d_in[4];   // (2,128,128)
    const float* proj_b = (const float*)d_in[5];   // (2,128)
    const float* ln_g   = (const float*)d_in[6];   // (128)
    const float* ln_b   = (const float*)d_in[7];   // (128)
    float* outp = (float*)d_out;

    float *qkvbuf, *attbuf, *y1, *y2;
    cudaGetSymbolAddress((void**)&qkvbuf, g_qkv);
    cudaGetSymbolAddress((void**)&attbuf, g_att);
    cudaGetSymbolAddress((void**)&y1, g_y1);
    cudaGetSymbolAddress((void**)&y2, g_y2);

    dim3 gq(NTOK/64, (3*CC)/64);   // 128 x 6
    dim3 gp(NTOK/64, CC/64);       // 128 x 2
    const int RPB_L = NH*13*13;

    // ---- layer 0 ----
    sgemm_kernel<<<gq, 256>>>(x, 1, qkv_w + 0, qkv_b + 0, qkvbuf, 3*CC);
    attn_kernel<<<NTOK, 128>>>(qkvbuf, rpb + 0, attbuf);
    sgemm_kernel<<<gp, 256>>>(attbuf, 0, proj_w + 0, proj_b + 0, y1, CC);

    // ---- layer 1 ----
    sgemm_kernel<<<gq, 256>>>(y1, 0, qkv_w + 3*CC*CC, qkv_b + 3*CC, qkvbuf, 3*CC);
    attn_kernel<<<NTOK, 128>>>(qkvbuf, rpb + RPB_L, attbuf);
    sgemm_kernel<<<gp, 256>>>(attbuf, 0, proj_w + CC*CC, proj_b + CC, y2, CC);

    // ---- LN + transpose ----
    ln_kernel<<<BB*HH, 256>>>(y2, ln_g, ln_b, outp);
}